// round 10
// baseline (speedup 1.0000x reference)
#include <cuda_runtime.h>
#include <stdint.h>

// BasedKernel feature map, d=16:
//   out[row, 0]        = 1
//   out[row, 1..16]    = x[row, j-1] * 0.5
//   out[row, 17+idx]   = x[row, idx>>4] * x[row, idx&15] * SC2,  idx = 0..255
//
// R10: line-aligned TMA flush. 32 rows/block = 34944B = exactly 273 L2
// lines, so every bulk store is 128B-aligned at BOTH ends (R4's 8736B
// transfers started/ended mid-line: 8736%128=32, forcing partial-line
// writes at every block boundary). 256 threads, each warp computes 4 rows
// (independent chains -> ILP), one TMA bulk per block.

#define SC2 0.17677669529663687f

#define ROWS_PER_BLOCK 32
#define ROWS_PER_WARP  4
#define THREADS        256
#define FLOATS_PER_BLOCK (ROWS_PER_BLOCK * 273)      // 8736
#define BYTES_PER_BLOCK  (FLOATS_PER_BLOCK * 4)      // 34944 = 273*128

__global__ void __launch_bounds__(THREADS, 6)
based_feature_kernel(const float* __restrict__ x,
                     float* __restrict__ out)
{
    __shared__ __align__(128) float buf[FLOATS_PER_BLOCK];

    const int tid  = threadIdx.x;
    const int warp = tid >> 5;                 // 0..7
    const int lane = tid & 31;
    const int hi   = lane >> 4;                // 0 or 1
    const int k_lo = lane & 15;

    const int row_base = blockIdx.x * ROWS_PER_BLOCK + warp * ROWS_PER_WARP;

    // ---- Phase 1: each warp computes 4 rows (independent chains) ----
#pragma unroll
    for (int r = 0; r < ROWS_PER_WARP; ++r) {
        const int row = row_base + r;
        const float* xr = x + (size_t)row * 16;
        float v = (lane < 16) ? __ldg(xr + lane) : 0.0f;

        float* o = buf + (warp * ROWS_PER_WARP + r) * 273;

        // Convergent shfl first (full warp participates).
        const float b2 = __shfl_sync(0xffffffffu, v, k_lo) * SC2;

        // Header (shfl-free, predicated stores only).
        if (lane < 16) o[1 + lane] = v * 0.5f;
        if (lane == 16) o[0] = 1.0f;

        // Quadratic: idx = 32m + lane, i = 2m + hi, k = lane&15.
#pragma unroll
        for (int m = 0; m < 8; ++m) {
            const float a = __shfl_sync(0xffffffffu, v, 2 * m + hi);
            o[17 + 32 * m + lane] = a * b2;
        }
    }

    __syncthreads();

    // ---- Phase 2: single line-aligned 1-D TMA bulk store (bypasses L1) ----
    if (tid == 0) {
        uint32_t saddr;
        asm volatile(
            "{ .reg .u64 t; cvta.to.shared.u64 t, %1; cvt.u32.u64 %0, t; }"
            : "=r"(saddr) : "l"(buf));

        float* g = out + (size_t)blockIdx.x * FLOATS_PER_BLOCK;

        asm volatile("fence.proxy.async.shared::cta;" ::: "memory");
        asm volatile(
            "cp.async.bulk.global.shared::cta.bulk_group [%0], [%1], %2;"
            :: "l"(g), "r"(saddr), "n"(BYTES_PER_BLOCK) : "memory");
        asm volatile("cp.async.bulk.commit_group;" ::: "memory");
        asm volatile("cp.async.bulk.wait_group.read 0;" ::: "memory");
    }
}

extern "C" void kernel_launch(void* const* d_in, const int* in_sizes, int n_in,
                              void* d_out, int out_size)
{
    const float* x = (const float*)d_in[0];
    float* out = (float*)d_out;

    const int n_rows = in_sizes[0] / 16;              // 262144
    const int blocks = n_rows / ROWS_PER_BLOCK;       // 8192 (exact)

    based_feature_kernel<<<blocks, THREADS>>>(x, out);
}

// round 11
// speedup vs baseline: 1.0250x; 1.0250x over previous
#include <cuda_runtime.h>
#include <stdint.h>

// BasedKernel feature map, d=16:
//   out[row, 0]        = 1
//   out[row, 1..16]    = x[row, j-1] * 0.5
//   out[row, 17+idx]   = x[row, idx>>4] * x[row, idx&15] * SC2,  idx = 0..255
//
// FINAL (= R4, best measured: 49.9us bench / 45.7us ncu, DRAM 67%,
// 6.26 TB/s effective write stream ~ HBM write ceiling).
//
// Structure: one warp per row, x resident one-value-per-lane (NO dynamically
// indexed local array -- that spills to local memory and was the hidden
// l1tex ceiling in early rounds). Quadratic indices decompose as
// idx = 32m + lane -> i = 2m + (lane>>4), k = lane&15; the k-operand is one
// hoisted shfl premultiplied by SC2, the i-operand is one shfl per m.
// Rows staged in smem (contiguous conflict-free STS), flushed with a single
// 1-D TMA bulk store per block: zero LDS/STG/L1-wavefront cost on the 286MB
// output stream. Verified-losing alternatives: 16-row/512-thread CTAs,
// persistent pipelined TMA, 2-tile double buffer, float4 STG flush,
// 32-row line-aligned TMA -- all neutral or worse.

#define SC2 0.17677669529663687f

#define ROWS_PER_BLOCK 8
#define THREADS        256
#define FLOATS_PER_BLOCK (ROWS_PER_BLOCK * 273)      // 2184
#define BYTES_PER_BLOCK  (FLOATS_PER_BLOCK * 4)      // 8736, multiple of 16

__global__ void __launch_bounds__(THREADS, 8)
based_feature_kernel(const float* __restrict__ x,
                     float* __restrict__ out)
{
    __shared__ __align__(16) float buf[FLOATS_PER_BLOCK];

    const int tid  = threadIdx.x;
    const int warp = tid >> 5;                 // 0..7 = local row
    const int lane = tid & 31;
    const int row  = blockIdx.x * ROWS_PER_BLOCK + warp;

    // ---- Phase 1: one row per warp, x resident one-value-per-lane ----
    const float* xr = x + (size_t)row * 16;
    float v = (lane < 16) ? __ldg(xr + lane) : 0.0f;

    float* o = buf + warp * 273;

    // Convergent shfls (full warp participates; never inside divergence).
    const float b2 = __shfl_sync(0xffffffffu, v, lane & 15) * SC2;  // k-operand
    const int   hi = lane >> 4;                                     // 0 or 1

    // Header (shfl-free, predicated stores only).
    if (lane < 16) o[1 + lane] = v * 0.5f;
    if (lane == 16) o[0] = 1.0f;

    // Quadratic part: idx = 32m + lane, i = 2m + hi, k = lane&15.
#pragma unroll
    for (int m = 0; m < 8; ++m) {
        const float a = __shfl_sync(0xffffffffu, v, 2 * m + hi);
        o[17 + 32 * m + lane] = a * b2;
    }

    __syncthreads();

    // ---- Phase 2: single 1-D TMA bulk store smem -> gmem (bypasses L1) ----
    if (tid == 0) {
        uint32_t saddr;
        asm volatile(
            "{ .reg .u64 t; cvta.to.shared.u64 t, %1; cvt.u32.u64 %0, t; }"
            : "=r"(saddr) : "l"(buf));

        float* g = out + (size_t)blockIdx.x * FLOATS_PER_BLOCK;
        const int nbytes = BYTES_PER_BLOCK;

        // Order generic-proxy smem writes before the async-proxy read.
        asm volatile("fence.proxy.async.shared::cta;" ::: "memory");
        asm volatile(
            "cp.async.bulk.global.shared::cta.bulk_group [%0], [%1], %2;"
            :: "l"(g), "r"(saddr), "r"(nbytes) : "memory");
        asm volatile("cp.async.bulk.commit_group;" ::: "memory");
        // Keep the CTA (and its smem) alive until the bulk read completes.
        asm volatile("cp.async.bulk.wait_group.read 0;" ::: "memory");
    }
}

extern "C" void kernel_launch(void* const* d_in, const int* in_sizes, int n_in,
                              void* d_out, int out_size)
{
    const float* x = (const float*)d_in[0];
    float* out = (float*)d_out;

    const int n_rows = in_sizes[0] / 16;              // 262144
    const int blocks = n_rows / ROWS_PER_BLOCK;       // 32768 (exact)

    based_feature_kernel<<<blocks, THREADS>>>(x, out);
}

// round 12
// speedup vs baseline: 1.0369x; 1.0117x over previous
#include <cuda_runtime.h>
#include <stdint.h>

// BasedKernel feature map, d=16:
//   out[row, 0]        = 1
//   out[row, 1..16]    = x[row, j-1] * 0.5
//   out[row, 17+idx]   = x[row, idx>>4] * x[row, idx&15] * SC2,  idx = 0..255
//
// R12: R4 structure (proven: one warp per row, one-value-per-lane x,
// hoisted-shfl quadratic, smem staging, single 1-D TMA bulk flush) at the
// smallest tile on the CTA-size axis: 4 rows / 128 threads. Measured trend
// (8 rows: 45.7us, 16: 48.5, 32: 46.2) favors small tiles -- finer
// scheduling granularity and a shorter blocking TMA-drain tail per CTA
// slot, with 2x more CTAs interleaving those tails per SM.

#define SC2 0.17677669529663687f

#define ROWS_PER_BLOCK 4
#define THREADS        128
#define FLOATS_PER_BLOCK (ROWS_PER_BLOCK * 273)      // 1092
#define BYTES_PER_BLOCK  (FLOATS_PER_BLOCK * 4)      // 4368, multiple of 16

__global__ void __launch_bounds__(THREADS, 16)
based_feature_kernel(const float* __restrict__ x,
                     float* __restrict__ out)
{
    __shared__ __align__(16) float buf[FLOATS_PER_BLOCK];

    const int tid  = threadIdx.x;
    const int warp = tid >> 5;                 // 0..3 = local row
    const int lane = tid & 31;
    const int row  = blockIdx.x * ROWS_PER_BLOCK + warp;

    // ---- Phase 1: one row per warp, x resident one-value-per-lane ----
    const float* xr = x + (size_t)row * 16;
    float v = (lane < 16) ? __ldg(xr + lane) : 0.0f;

    float* o = buf + warp * 273;

    // Convergent shfls (full warp participates; never inside divergence).
    const float b2 = __shfl_sync(0xffffffffu, v, lane & 15) * SC2;  // k-operand
    const int   hi = lane >> 4;                                     // 0 or 1

    // Header (shfl-free, predicated stores only).
    if (lane < 16) o[1 + lane] = v * 0.5f;
    if (lane == 16) o[0] = 1.0f;

    // Quadratic part: idx = 32m + lane, i = 2m + hi, k = lane&15.
#pragma unroll
    for (int m = 0; m < 8; ++m) {
        const float a = __shfl_sync(0xffffffffu, v, 2 * m + hi);
        o[17 + 32 * m + lane] = a * b2;
    }

    __syncthreads();

    // ---- Phase 2: single 1-D TMA bulk store smem -> gmem (bypasses L1) ----
    if (tid == 0) {
        uint32_t saddr;
        asm volatile(
            "{ .reg .u64 t; cvta.to.shared.u64 t, %1; cvt.u32.u64 %0, t; }"
            : "=r"(saddr) : "l"(buf));

        float* g = out + (size_t)blockIdx.x * FLOATS_PER_BLOCK;
        const int nbytes = BYTES_PER_BLOCK;

        // Order generic-proxy smem writes before the async-proxy read.
        asm volatile("fence.proxy.async.shared::cta;" ::: "memory");
        asm volatile(
            "cp.async.bulk.global.shared::cta.bulk_group [%0], [%1], %2;"
            :: "l"(g), "r"(saddr), "r"(nbytes) : "memory");
        asm volatile("cp.async.bulk.commit_group;" ::: "memory");
        // Keep the CTA (and its smem) alive until the bulk read completes.
        asm volatile("cp.async.bulk.wait_group.read 0;" ::: "memory");
    }
}

extern "C" void kernel_launch(void* const* d_in, const int* in_sizes, int n_in,
                              void* d_out, int out_size)
{
    const float* x = (const float*)d_in[0];
    float* out = (float*)d_out;

    const int n_rows = in_sizes[0] / 16;              // 262144
    const int blocks = n_rows / ROWS_PER_BLOCK;       // 65536 (exact)

    based_feature_kernel<<<blocks, THREADS>>>(x, out);
}